// round 4
// baseline (speedup 1.0000x reference)
#include <cuda_runtime.h>

// Problem constants
#define BATCH 512
#define TLEN  256
#define HID   512
#define G4    2048   // 4*HID
#define HALF  256
#define TGT   28

// GEMM tiling
#define BM 64
#define BN 64
#define BK 16
#define NTHREADS 256
#define MTILES (BATCH / BM)   // 8
#define NTILES (G4 / BN)      // 32
#define NCTAS  (MTILES * NTILES) // 256
#define PAD 4
#define SMSTR (BM + PAD)      // 68 floats per smem row (272B, 16B-aligned)

// ---------------- device scratch (no allocations allowed) ----------------
__device__ __align__(16) float g_h[2][BATCH * HID];   // double-buffered hidden state
__device__ __align__(16) float g_Wp[G4 * HID];        // W_hh reordered: row r = k*4 + gate
__device__ __align__(16) float g_wihp[G4];            // W_ih reordered
__device__ __align__(16) float g_biasp[G4];           // (b_ih + b_hh) reordered
__device__ __align__(16) float g_hid[BATCH * HALF];   // fc1 output
__device__ unsigned int g_barcnt;                     // zero-initialized
__device__ volatile unsigned int g_bargen;

// ---------------- grid-wide barrier (sense-reversing) ----------------
__device__ __forceinline__ void gridbar() {
    __threadfence();      // make this thread's global writes visible
    __syncthreads();      // CTA-level: everyone's writes ordered before tid0 proceeds
    if (threadIdx.x == 0) {
        unsigned int gen = g_bargen;           // snapshot BEFORE arriving
        if (atomicAdd(&g_barcnt, 1u) == NCTAS - 1u) {
            g_barcnt = 0u;
            __threadfence();
            g_bargen = gen + 1u;               // release
        } else {
            while (g_bargen == gen) { }        // spin (volatile -> L2 reads)
            __threadfence();                   // acquire
        }
    }
    __syncthreads();
}

__device__ __forceinline__ float sigmoidf(float x) {
    return 1.0f / (1.0f + __expf(-x));
}

__global__ __launch_bounds__(NTHREADS, 2)
void lstm_persistent_kernel(
    const float* __restrict__ seq,    // [B, T, 1]
    const float* __restrict__ W_ih,   // [4H, 1]
    const float* __restrict__ W_hh,   // [4H, H]
    const float* __restrict__ b_ih,   // [4H]
    const float* __restrict__ b_hh,   // [4H]
    const float* __restrict__ fc1w,   // [HALF, H]
    const float* __restrict__ fc1b,   // [HALF]
    const float* __restrict__ fc2w,   // [TGT, HALF]
    const float* __restrict__ fc2b,   // [TGT]
    float* __restrict__ out)          // [B, TGT, 1]
{
    __shared__ __align__(16) float As[2][BK][SMSTR];
    __shared__ __align__(16) float Bs[2][BK][SMSTR];
    __shared__ __align__(16) float hs[2][HID];   // for fc1 tail

    const int tid = threadIdx.x;
    const int cta = blockIdx.x;
    const int gid = cta * NTHREADS + tid;
    const int gsz = NCTAS * NTHREADS;            // 65536

    // ---------------- prep: reorder weights, zero state ----------------
    // Wp[(k*4+g)*H + j] = W_hh[(g*512 + k)*H + j]
    for (int e = gid; e < G4 * HID; e += gsz) {
        int r = e >> 9;          // row (0..2047)
        int j = e & 511;         // col
        int k = r >> 2;
        int q = r & 3;
        g_Wp[e] = W_hh[((q << 9) + k) * HID + j];
    }
    for (int e = gid; e < G4; e += gsz) {
        int k = e >> 2, q = e & 3;
        int src = (q << 9) + k;
        g_wihp[e] = W_ih[src];
        g_biasp[e] = b_ih[src] + b_hh[src];
    }
    for (int e = gid; e < BATCH * HID; e += gsz) {
        g_h[0][e] = 0.0f;
    }
    gridbar();

    // ---------------- per-CTA tile geometry ----------------
    const int tileM = cta / NTILES;
    const int tileN = cta % NTILES;
    const int b0 = tileM * BM;
    const int n0 = tileN * BN;

    const int tidm = tid & 15;          // 0..15 (batch dim)
    const int tidn = tid >> 4;          // 0..15 (gate-row dim)
    const int m0 = 2 * tidm;            // m-fragment: {m0, m0+1, m1, m1+1}
    const int m1 = 32 + 2 * tidm;
    const int nb = n0 + tidn * 4;       // 4 consecutive reordered rows = gates of unit:
    const int kunit = nb >> 2;          // hidden unit owned by this thread

    const int ms[4] = { m0, m0 + 1, m1, m1 + 1 };
    int hoff[4], soff[4];
    #pragma unroll
    for (int i = 0; i < 4; i++) {
        hoff[i] = (b0 + ms[i]) * HID + kunit;
        soff[i] = (b0 + ms[i]) * TLEN;
    }

    // loader mapping: 256 threads load 64 rows x 16 cols as float4
    const int lrow = tid >> 2;          // 0..63
    const int lcol = (tid & 3) << 2;    // 0,4,8,12

    const float4 wih4  = *(const float4*)&g_wihp[nb];
    const float4 bias4 = *(const float4*)&g_biasp[nb];

    float creg[4] = {0.f, 0.f, 0.f, 0.f};   // cell state lives in registers all T steps

    // ---------------- recurrent loop ----------------
    for (int t = 0; t < TLEN; ++t) {
        const float* hin = g_h[t & 1];
        float* hout = g_h[(t & 1) ^ 1];

        float acc[4][4];
        #pragma unroll
        for (int i = 0; i < 4; i++)
            #pragma unroll
            for (int j = 0; j < 4; j++) acc[i][j] = 0.0f;

        // prologue: chunk 0 -> smem buf 0
        {
            float4 av = *(const float4*)&hin[(b0 + lrow) * HID + lcol];
            float4 bv = *(const float4*)&g_Wp[(n0 + lrow) * HID + lcol];
            As[0][lcol + 0][lrow] = av.x; As[0][lcol + 1][lrow] = av.y;
            As[0][lcol + 2][lrow] = av.z; As[0][lcol + 3][lrow] = av.w;
            Bs[0][lcol + 0][lrow] = bv.x; Bs[0][lcol + 1][lrow] = bv.y;
            Bs[0][lcol + 2][lrow] = bv.z; Bs[0][lcol + 3][lrow] = bv.w;
        }
        __syncthreads();

        int cur = 0;
        #pragma unroll 1
        for (int kt = 0; kt < HID / BK; ++kt) {
            float4 av2, bv2;
            const bool more = (kt + 1 < HID / BK);
            if (more) {
                int kk = (kt + 1) * BK;
                av2 = *(const float4*)&hin[(b0 + lrow) * HID + kk + lcol];
                bv2 = *(const float4*)&g_Wp[(n0 + lrow) * HID + kk + lcol];
            }
            // compute on current buffer
            #pragma unroll
            for (int k = 0; k < BK; ++k) {
                float2 a01 = *(const float2*)&As[cur][k][m0];
                float2 a23 = *(const float2*)&As[cur][k][m1];
                float4 b4  = *(const float4*)&Bs[cur][k][tidn * 4];
                float am[4] = { a01.x, a01.y, a23.x, a23.y };
                float bn[4] = { b4.x, b4.y, b4.z, b4.w };
                #pragma unroll
                for (int i = 0; i < 4; i++)
                    #pragma unroll
                    for (int j = 0; j < 4; j++)
                        acc[i][j] += am[i] * bn[j];
            }
            if (more) {
                int nxt = cur ^ 1;
                As[nxt][lcol + 0][lrow] = av2.x; As[nxt][lcol + 1][lrow] = av2.y;
                As[nxt][lcol + 2][lrow] = av2.z; As[nxt][lcol + 3][lrow] = av2.w;
                Bs[nxt][lcol + 0][lrow] = bv2.x; Bs[nxt][lcol + 1][lrow] = bv2.y;
                Bs[nxt][lcol + 2][lrow] = bv2.z; Bs[nxt][lcol + 3][lrow] = bv2.w;
            }
            __syncthreads();
            cur ^= 1;
        }

        // epilogue: gates -> activations -> c,h update (gate order i,f,g,o)
        #pragma unroll
        for (int i = 0; i < 4; i++) {
            float xv = seq[soff[i] + t];
            float gi = acc[i][0] + xv * wih4.x + bias4.x;
            float gf = acc[i][1] + xv * wih4.y + bias4.y;
            float gg = acc[i][2] + xv * wih4.z + bias4.z;
            float go = acc[i][3] + xv * wih4.w + bias4.w;
            float I = sigmoidf(gi);
            float F = sigmoidf(gf);
            float G = tanhf(gg);
            float O = sigmoidf(go);
            float cc = F * creg[i] + I * G;
            creg[i] = cc;
            hout[hoff[i]] = O * tanhf(cc);
        }

        gridbar();
    }

    // ---------------- fc1: hid = relu(h @ fc1w^T + fc1b) ----------------
    {
        const float* hfin = g_h[TLEN & 1];   // final h is in buffer 0
        int bb = cta * 2;                    // 256 CTAs x 2 batch rows = 512
        for (int e = tid; e < 2 * HID; e += NTHREADS)
            hs[e >> 9][e & 511] = hfin[(bb + (e >> 9)) * HID + (e & 511)];
        __syncthreads();

        int n = tid;                         // HALF == NTHREADS == 256
        const float* wr = fc1w + n * HID;
        float s0 = fc1b[n], s1 = s0;
        #pragma unroll 8
        for (int k = 0; k < HID; ++k) {
            float w = wr[k];
            s0 += hs[0][k] * w;
            s1 += hs[1][k] * w;
        }
        g_hid[bb * HALF + n]       = fmaxf(s0, 0.0f);
        g_hid[(bb + 1) * HALF + n] = fmaxf(s1, 0.0f);
    }
    gridbar();

    // ---------------- fc2: out = hid @ fc2w^T + fc2b ----------------
    for (int o = gid; o < BATCH * TGT; o += gsz) {
        int b = o / TGT;
        int tt = o - b * TGT;
        const float* hr = g_hid + b * HALF;
        const float* wr = fc2w + tt * HALF;
        float s = fc2b[tt];
        #pragma unroll 8
        for (int k = 0; k < HALF; ++k) s += hr[k] * wr[k];
        out[o] = s;
    }
}

extern "C" void kernel_launch(void* const* d_in, const int* in_sizes, int n_in,
                              void* d_out, int out_size) {
    (void)in_sizes; (void)n_in; (void)out_size;
    lstm_persistent_kernel<<<NCTAS, NTHREADS>>>(
        (const float*)d_in[0],  // sequence
        (const float*)d_in[1],  // W_ih
        (const float*)d_in[2],  // W_hh
        (const float*)d_in[3],  // b_ih
        (const float*)d_in[4],  // b_hh
        (const float*)d_in[5],  // fc1_w
        (const float*)d_in[6],  // fc1_b
        (const float*)d_in[7],  // fc2_w
        (const float*)d_in[8],  // fc2_b
        (float*)d_out);
}

// round 6
// speedup vs baseline: 3.0898x; 3.0898x over previous
#include <cuda_runtime.h>
#include <cuda_bf16.h>

#define BATCH 512
#define TLEN  256
#define HID   512
#define G4    2048
#define HALF  256
#define TGT   28

#define NTHREADS 256
#define NCTAS 128
#define GSZ (NCTAS * NTHREADS)
#define WSMEM_BYTES 131072   // 32 k16 x 8 n8 x 512B (hi+lo W fragments)

// ---------------- device scratch ----------------
// A(h) fragments per (m16,k16): 1024B = [hi: lane*16][lo: +512 + lane*16], uint4 = {r0,r1,r2,r3}
__device__ __align__(16) unsigned char g_hfrag[2][1 << 20];
// B(W) fragments per (n8,k16): 512B = lane*16 : {hi_r0, hi_r1, lo_r0, lo_r1}
__device__ __align__(16) unsigned char g_Wfrag[4 << 20];
__device__ __align__(16) float g_hfin[BATCH * HID];
__device__ __align__(16) float g_hid[BATCH * HALF];
__device__ unsigned int g_barcnt;
__device__ volatile unsigned int g_bargen;

__device__ __forceinline__ void gridbar() {
    __threadfence();
    __syncthreads();
    if (threadIdx.x == 0) {
        unsigned int gen = g_bargen;
        if (atomicAdd(&g_barcnt, 1u) == NCTAS - 1u) {
            g_barcnt = 0u;
            __threadfence();
            g_bargen = gen + 1u;
        } else {
            while (g_bargen == gen) { }
            __threadfence();
        }
    }
    __syncthreads();
}

__device__ __forceinline__ float sigf(float x)  { return 1.0f / (1.0f + __expf(-x)); }
__device__ __forceinline__ float tanhft(float x){ return 1.0f - 2.0f / (__expf(2.0f * x) + 1.0f); }

__device__ __forceinline__ unsigned int pack2(float a, float b) {
    __nv_bfloat16 ah = __float2bfloat16(a), bh = __float2bfloat16(b);
    return (unsigned int)__bfloat16_as_ushort(ah) |
           ((unsigned int)__bfloat16_as_ushort(bh) << 16);
}

#define MMA_BF16(c, A, B0, B1)                                              \
    asm volatile("mma.sync.aligned.m16n8k16.row.col.f32.bf16.bf16.f32 "     \
                 "{%0,%1,%2,%3}, {%4,%5,%6,%7}, {%8,%9}, {%0,%1,%2,%3};"    \
                 : "+f"(c[0]), "+f"(c[1]), "+f"(c[2]), "+f"(c[3])           \
                 : "r"(A.x), "r"(A.y), "r"(A.z), "r"(A.w), "r"(B0), "r"(B1))

__global__ __launch_bounds__(NTHREADS, 1)
void lstm_mma_kernel(
    const float* __restrict__ seq,  const float* __restrict__ W_ih,
    const float* __restrict__ W_hh, const float* __restrict__ b_ih,
    const float* __restrict__ b_hh, const float* __restrict__ fc1w,
    const float* __restrict__ fc1b, const float* __restrict__ fc2w,
    const float* __restrict__ fc2b, float* __restrict__ out)
{
    extern __shared__ unsigned char wsm[];                 // 128KB W fragments
    __shared__ __align__(16) float stage[8][16][18];       // per-warp h repack tile
    __shared__ __align__(16) float4 sm_wih[16], sm_bias[16];
    __shared__ __align__(16) float hs[4][HID];             // fc1 tail

    const int tid  = threadIdx.x;
    const int cta  = blockIdx.x;
    const int gid  = cta * NTHREADS + tid;
    const int lane = tid & 31;
    const int wti  = tid >> 5;
    const int gq   = lane >> 2;
    const int tg   = lane & 3;

    // ---- prep: W fragments (split + gate-interleave reorder). col n -> gate/unit:
    // blk=n/16, w16=n%16, gate=((w16>>3)<<1)|(w16&1), unit=blk*4+((w16&7)>>1)
    for (int it = gid; it < 256 * 32 * 32; it += GSZ) {
        int ln  = it & 31;
        int k16 = (it >> 5) & 31;
        int n8  = it >> 10;
        int n   = n8 * 8 + (ln >> 2);
        int w16 = n & 15;
        int gate = ((w16 >> 3) << 1) | (w16 & 1);
        int unit = (n >> 4) * 4 + ((w16 & 7) >> 1);
        const float* wr = W_hh + (gate * HID + unit) * HID + k16 * 16 + (tg << 1);
        float2 p0 = *(const float2*)wr;          // reg0: k, k+1
        float2 p1 = *(const float2*)(wr + 8);    // reg1: k+8, k+9
        float h0x = __bfloat162float(__float2bfloat16(p0.x));
        float h0y = __bfloat162float(__float2bfloat16(p0.y));
        float h1x = __bfloat162float(__float2bfloat16(p1.x));
        float h1y = __bfloat162float(__float2bfloat16(p1.y));
        uint4 v;
        v.x = pack2(p0.x, p0.y);
        v.y = pack2(p1.x, p1.y);
        v.z = pack2(p0.x - h0x, p0.y - h0y);
        v.w = pack2(p1.x - h1x, p1.y - h1y);
        *(uint4*)(g_Wfrag + (((n8 << 5) + k16) << 9) + ln * 16) = v;
    }
    // zero h fragments buffer 0 (h = 0)
    {
        uint4 z = make_uint4(0, 0, 0, 0);
        uint4* hz = (uint4*)g_hfrag[0];
        for (int e = gid; e < (1 << 16); e += GSZ) hz[e] = z;
    }
    gridbar();

    // ---- per-CTA geometry ----
    const int tileM = cta >> 5;            // 0..3
    const int tileN = cta & 31;            // 0..31
    const int b0    = tileM * 128;
    const int m16g  = tileM * 8 + wti;

    // copy this CTA's W fragments to smem (once; smem k16-major)
    {
        uint4* s4 = (uint4*)wsm;
        const uint4* g4 = (const uint4*)g_Wfrag;
        for (int e = tid; e < WSMEM_BYTES / 16; e += NTHREADS) {
            int w = e & 31, c = e >> 5;
            int kt = c >> 3, j = c & 7;
            s4[e] = __ldcg(&g4[(((tileN * 8 + j) << 5) + kt) * 32 + w]);
        }
    }
    // per-unit x-weight / bias (gate order i,f,g,o)
    for (int e = tid; e < 64; e += NTHREADS) {
        int u = e >> 2, g = e & 3;
        int ku = tileN * 16 + u;
        ((float*)sm_wih)[e]  = W_ih[g * HID + ku];
        ((float*)sm_bias)[e] = b_ih[g * HID + ku] + b_hh[g * HID + ku];
    }
    __syncthreads();

    float creg[2][4];
    #pragma unroll
    for (int r = 0; r < 2; ++r)
        #pragma unroll
        for (int j = 0; j < 4; ++j) creg[r][j] = 0.0f;

    const int row_base = b0 + wti * 16 + gq;

    // ---- recurrent loop ----
    for (int t = 0; t < TLEN; ++t) {
        const unsigned char* hin  = g_hfrag[t & 1];
        unsigned char*       hout = g_hfrag[(t + 1) & 1];
        const unsigned char* abase = hin + ((size_t)(m16g * 32) << 10) + lane * 16;

        float acc[8][4];
        #pragma unroll
        for (int j = 0; j < 8; ++j)
            #pragma unroll
            for (int c = 0; c < 4; ++c) acc[j][c] = 0.0f;

        uint4 a0[2], a1[2];
        a0[0] = __ldcg((const uint4*)(abase));
        a1[0] = __ldcg((const uint4*)(abase + 512));
        a0[1] = __ldcg((const uint4*)(abase + 1024));
        a1[1] = __ldcg((const uint4*)(abase + 1536));

        #pragma unroll 2
        for (int kt = 0; kt < 32; ++kt) {
            const int s = kt & 1;
            uint4 bw[8];
            #pragma unroll
            for (int j = 0; j < 8; ++j)
                bw[j] = *(const uint4*)(wsm + (((kt << 3) + j) << 9) + lane * 16);
            #pragma unroll
            for (int j = 0; j < 8; ++j) MMA_BF16(acc[j], a0[s], bw[j].x, bw[j].y); // h_hi * w_hi
            #pragma unroll
            for (int j = 0; j < 8; ++j) MMA_BF16(acc[j], a1[s], bw[j].x, bw[j].y); // h_lo * w_hi
            #pragma unroll
            for (int j = 0; j < 8; ++j) MMA_BF16(acc[j], a0[s], bw[j].z, bw[j].w); // h_hi * w_lo
            if (kt + 2 < 32) {
                const unsigned char* p = abase + ((size_t)(kt + 2) << 10);
                a0[s] = __ldcg((const uint4*)p);
                a1[s] = __ldcg((const uint4*)(p + 512));
            }
        }

        // ---- epilogue: gates -> c,h ; repack h into A fragments ----
        #pragma unroll
        for (int rh = 0; rh < 2; ++rh) {
            float xv = seq[(row_base + rh * 8) * TLEN + t];
            #pragma unroll
            for (int jj = 0; jj < 4; ++jj) {
                float4 wv = sm_wih[jj * 4 + tg];
                float4 bv = sm_bias[jj * 4 + tg];
                float gi = acc[2*jj  ][rh*2+0] + xv * wv.x + bv.x;
                float gf = acc[2*jj  ][rh*2+1] + xv * wv.y + bv.y;
                float gg = acc[2*jj+1][rh*2+0] + xv * wv.z + bv.z;
                float go = acc[2*jj+1][rh*2+1] + xv * wv.w + bv.w;
                float cc = sigf(gf) * creg[rh][jj] + sigf(gi) * tanhft(gg);
                creg[rh][jj] = cc;
                float hv = sigf(go) * tanhft(cc);
                stage[wti][gq + rh * 8][jj * 4 + tg] = hv;
                if (t == TLEN - 1)
                    g_hfin[(row_base + rh * 8) * HID + tileN * 16 + jj * 4 + tg] = hv;
            }
        }
        __syncwarp();
        unsigned int fhi[4], flo[4];
        #pragma unroll
        for (int r = 0; r < 4; ++r) {
            int m  = gq + (r & 1) * 8;
            int k0 = tg * 2 + (r >> 1) * 8;
            float a = stage[wti][m][k0];
            float b = stage[wti][m][k0 + 1];
            float ah = __bfloat162float(__float2bfloat16(a));
            float bh = __bfloat162float(__float2bfloat16(b));
            fhi[r] = pack2(a, b);
            flo[r] = pack2(a - ah, b - bh);
        }
        unsigned char* op = hout + ((size_t)(m16g * 32 + tileN) << 10) + lane * 16;
        *(uint4*)op         = make_uint4(fhi[0], fhi[1], fhi[2], fhi[3]);
        *(uint4*)(op + 512) = make_uint4(flo[0], flo[1], flo[2], flo[3]);

        gridbar();
    }

    // ---- fc1: hid = relu(h @ fc1w^T + fc1b), 4 batch rows per CTA ----
    {
        int bb = cta * 4;
        for (int e = tid; e < 4 * HID; e += NTHREADS)
            hs[e >> 9][e & 511] = g_hfin[(bb + (e >> 9)) * HID + (e & 511)];
        __syncthreads();
        int n = tid;                         // HALF == 256 == NTHREADS
        const float* wr = fc1w + n * HID;
        float s0 = fc1b[n], s1 = s0, s2 = s0, s3 = s0;
        #pragma unroll 8
        for (int k = 0; k < HID; ++k) {
            float w = wr[k];
            s0 += hs[0][k] * w; s1 += hs[1][k] * w;
            s2 += hs[2][k] * w; s3 += hs[3][k] * w;
        }
        g_hid[(bb + 0) * HALF + n] = fmaxf(s0, 0.0f);
        g_hid[(bb + 1) * HALF + n] = fmaxf(s1, 0.0f);
        g_hid[(bb + 2) * HALF + n] = fmaxf(s2, 0.0f);
        g_hid[(bb + 3) * HALF + n] = fmaxf(s3, 0.0f);
    }
    gridbar();

    // ---- fc2 ----
    for (int o = gid; o < BATCH * TGT; o += GSZ) {
        int b = o / TGT;
        int tt = o - b * TGT;
        const float* hr = g_hid + b * HALF;
        const float* wr = fc2w + tt * HALF;
        float s = fc2b[tt];
        #pragma unroll 8
        for (int k = 0; k < HALF; ++k) s += hr[k] * wr[k];
        out[o] = s;
    }
}

extern "C" void kernel_launch(void* const* d_in, const int* in_sizes, int n_in,
                              void* d_out, int out_size) {
    (void)in_sizes; (void)n_in; (void)out_size;
    cudaFuncSetAttribute(lstm_mma_kernel,
                         cudaFuncAttributeMaxDynamicSharedMemorySize, WSMEM_BYTES);
    lstm_mma_kernel<<<NCTAS, NTHREADS, WSMEM_BYTES>>>(
        (const float*)d_in[0], (const float*)d_in[1], (const float*)d_in[2],
        (const float*)d_in[3], (const float*)d_in[4], (const float*)d_in[5],
        (const float*)d_in[6], (const float*)d_in[7], (const float*)d_in[8],
        (float*)d_out);
}